// round 1
// baseline (speedup 1.0000x reference)
#include <cuda_runtime.h>
#include <math_constants.h>

#define NTOK 2304      // 48*48
#define CDIM 256
#define BSZ  4
#define NH   8
#define HD   32
#define SCALE 0.17677669529663687f   // 32^-0.5

// ---------------- scratch (device globals: allowed) ----------------
// attn index: 0 = img-query / radar-KV (uses uncertainty weight)
//             1 = radar-query / img-KV
__device__ float g_Q [2][BSZ*NH*NTOK*HD];   // (b,h,n,d)
__device__ float g_Kt[2][BSZ*NH*HD*NTOK];   // (b,h,d,n)  d-major for coalesced attn loads
__device__ float g_V [2][BSZ*NH*NTOK*HD];   // (b,h,n,d)
__device__ float g_AttO[2][BSZ*NTOK*CDIM];  // (b,n,c) pre-projection

// ---------------- QKV projection GEMM ----------------
// out[n,c'] = sum_c X[b,c,n] * W[c,c']      (X is channel-major: perfect for A-tile loads)
// kind 0: write Q layout.  kind 1: cols 0..255 -> Kt, cols 256..511 -> V.
__global__ void proj_qkv_kernel(const float* __restrict__ X, const float* __restrict__ W,
                                int ncol, int kind, int attn)
{
    __shared__ float As[16][64];
    __shared__ float Bs[16][64];
    const int b  = blockIdx.z;
    const int m0 = blockIdx.x * 64;        // token tile
    const int n0 = blockIdx.y * 64;        // output-col tile
    const int tx = threadIdx.x, ty = threadIdx.y;
    const int tid = ty * 16 + tx;
    const float* Xb = X + (size_t)b * CDIM * NTOK;

    float acc[4][4] = {};
    for (int k0 = 0; k0 < CDIM; k0 += 16) {
        #pragma unroll
        for (int i = tid; i < 16*64; i += 256) {
            int k = i >> 6, m = i & 63;
            As[k][m] = Xb[(size_t)(k0 + k) * NTOK + m0 + m];
        }
        #pragma unroll
        for (int i = tid; i < 16*64; i += 256) {
            int k = i >> 6, n = i & 63;
            Bs[k][n] = W[(size_t)(k0 + k) * ncol + n0 + n];
        }
        __syncthreads();
        #pragma unroll
        for (int k = 0; k < 16; k++) {
            float4 a = *(const float4*)&As[k][ty * 4];
            float4 bb = *(const float4*)&Bs[k][tx * 4];
            float av[4] = {a.x, a.y, a.z, a.w};
            float bv[4] = {bb.x, bb.y, bb.z, bb.w};
            #pragma unroll
            for (int i = 0; i < 4; i++)
                #pragma unroll
                for (int j = 0; j < 4; j++)
                    acc[i][j] += av[i] * bv[j];
        }
        __syncthreads();
    }

    float* oQ  = g_Q[attn];
    float* oKt = g_Kt[attn];
    float* oV  = g_V[attn];
    #pragma unroll
    for (int i = 0; i < 4; i++) {
        int n = m0 + ty * 4 + i;                 // token index
        #pragma unroll
        for (int j = 0; j < 4; j++) {
            int cp = n0 + tx * 4 + j;            // output column
            float v = acc[i][j];
            if (kind == 0) {
                int h = cp >> 5, d = cp & 31;
                oQ[(((size_t)b * NH + h) * NTOK + n) * HD + d] = v;
            } else {
                if (cp < CDIM) {
                    int h = cp >> 5, d = cp & 31;
                    oKt[(((size_t)b * NH + h) * HD + d) * NTOK + n] = v;
                } else {
                    int c2 = cp - CDIM;
                    int h = c2 >> 5, d = c2 & 31;
                    oV[(((size_t)b * NH + h) * NTOK + n) * HD + d] = v;
                }
            }
        }
    }
}

// ---------------- attention (flash-style online softmax) ----------------
// grid: (NTOK/32, BSZ*NH, 2). block: 256 threads = 8 warps, 4 query rows/warp.
// each lane owns output dim d = lane.
__global__ void attn_kernel(const float* __restrict__ umask)
{
    const int attn = blockIdx.z;
    const int bh   = blockIdx.y;
    const int b    = bh >> 3;
    const int h    = bh & 7;
    const int row0 = blockIdx.x * 32;

    const float* Q  = g_Q[attn];
    const float* Kt = g_Kt[attn];
    const float* V  = g_V[attn];

    __shared__ float qs[32][HD];
    __shared__ float Ks[HD][64];
    __shared__ float Vs[64][HD];
    __shared__ float ps[8][4][32];

    const int tid  = threadIdx.x;
    const int warp = tid >> 5;
    const int lane = tid & 31;

    #pragma unroll
    for (int i = tid; i < 32 * HD; i += 256) {
        int r = i >> 5, d = i & 31;
        qs[r][d] = Q[((size_t)bh * NTOK + row0 + r) * HD + d];
    }

    float tw[4], runm[4], denom[4], acc[4];
    #pragma unroll
    for (int i = 0; i < 4; i++) {
        int n = row0 + warp * 4 + i;
        float f = SCALE;
        if (attn == 0) f *= 1.0f / (umask[(size_t)b * NTOK + n] + 1e-6f);
        tw[i] = f;
        runm[i] = -CUDART_INF_F;
        denom[i] = 0.f;
        acc[i] = 0.f;
    }

    const size_t ktbase = (size_t)bh * HD * NTOK;
    const size_t vbase  = (size_t)bh * NTOK * HD;

    for (int kb = 0; kb < NTOK; kb += 64) {
        __syncthreads();
        #pragma unroll
        for (int i = tid; i < HD * 64; i += 256) {
            int d = i >> 6, t = i & 63;
            Ks[d][t] = Kt[ktbase + (size_t)d * NTOK + kb + t];
        }
        #pragma unroll
        for (int i = tid; i < 64 * HD; i += 256) {
            int t = i >> 5, d = i & 31;
            Vs[t][d] = V[vbase + (size_t)(kb + t) * HD + d];
        }
        __syncthreads();

        #pragma unroll
        for (int sub = 0; sub < 2; sub++) {
            // scores for 4 rows, key = sub*32 + lane
            #pragma unroll
            for (int i = 0; i < 4; i++) {
                float s = 0.f;
                #pragma unroll
                for (int d = 0; d < HD; d++)
                    s += qs[warp * 4 + i][d] * Ks[d][sub * 32 + lane];
                s *= tw[i];
                float cm = s;
                #pragma unroll
                for (int o = 16; o > 0; o >>= 1)
                    cm = fmaxf(cm, __shfl_xor_sync(0xffffffffu, cm, o));
                float nm = fmaxf(runm[i], cm);
                float corr = __expf(runm[i] - nm);
                float pe   = __expf(s - nm);
                float psum = pe;
                #pragma unroll
                for (int o = 16; o > 0; o >>= 1)
                    psum += __shfl_xor_sync(0xffffffffu, psum, o);
                denom[i] = denom[i] * corr + psum;
                acc[i]  *= corr;
                runm[i]  = nm;
                ps[warp][i][lane] = pe;
            }
            __syncwarp();
            #pragma unroll 8
            for (int j = 0; j < 32; j++) {
                float vj = Vs[sub * 32 + j][lane];
                #pragma unroll
                for (int i = 0; i < 4; i++)
                    acc[i] += ps[warp][i][j] * vj;
            }
            __syncwarp();
        }
    }

    #pragma unroll
    for (int i = 0; i < 4; i++) {
        int n = row0 + warp * 4 + i;
        g_AttO[attn][((size_t)b * NTOK + n) * CDIM + h * HD + lane] = acc[i] / denom[i];
    }
}

// ---------------- output projection ----------------
// outT[b,c',n] = sum_c AttO[b,n,c] * Wp[c,c'] + bp[c']
__global__ void proj_out_kernel(const float* __restrict__ Wp, const float* __restrict__ bp,
                                int which, float* __restrict__ out)
{
    __shared__ float As[16][68];   // padded (transposed store)
    __shared__ float Bs[16][64];
    const int b  = blockIdx.z;
    const int m0 = blockIdx.x * 64;    // token tile
    const int n0 = blockIdx.y * 64;    // out-channel tile
    const int tx = threadIdx.x, ty = threadIdx.y;
    const int tid = ty * 16 + tx;
    const float* A = g_AttO[which] + (size_t)b * NTOK * CDIM;

    float acc[4][4] = {};
    for (int k0 = 0; k0 < CDIM; k0 += 16) {
        #pragma unroll
        for (int i = tid; i < 16 * 64; i += 256) {
            int m = i >> 4, k = i & 15;
            As[k][m] = A[(size_t)(m0 + m) * CDIM + k0 + k];
        }
        #pragma unroll
        for (int i = tid; i < 16 * 64; i += 256) {
            int k = i >> 6, n = i & 63;
            Bs[k][n] = Wp[(size_t)(k0 + k) * CDIM + n0 + n];
        }
        __syncthreads();
        #pragma unroll
        for (int k = 0; k < 16; k++) {
            float4 a = *(const float4*)&As[k][ty * 4];
            float4 bb = *(const float4*)&Bs[k][tx * 4];
            float av[4] = {a.x, a.y, a.z, a.w};
            float bv[4] = {bb.x, bb.y, bb.z, bb.w};
            #pragma unroll
            for (int i = 0; i < 4; i++)
                #pragma unroll
                for (int j = 0; j < 4; j++)
                    acc[i][j] += av[i] * bv[j];
        }
        __syncthreads();
    }

    float* outb = out + (size_t)b * CDIM * NTOK;
    #pragma unroll
    for (int j = 0; j < 4; j++) {
        int cp = n0 + tx * 4 + j;
        float bias = bp[cp];
        #pragma unroll
        for (int i = 0; i < 4; i++) {
            int n = m0 + ty * 4 + i;
            outb[(size_t)cp * NTOK + n] = acc[i][j] + bias;
        }
    }
}

// ---------------- launch ----------------
extern "C" void kernel_launch(void* const* d_in, const int* in_sizes, int n_in,
                              void* d_out, int out_size)
{
    const float* img   = (const float*)d_in[0];
    const float* radar = (const float*)d_in[1];
    const float* umask = (const float*)d_in[2];
    const float* Wq_img    = (const float*)d_in[3];
    const float* Wkv_radar = (const float*)d_in[4];
    const float* Wq_radar  = (const float*)d_in[5];
    const float* Wkv_img   = (const float*)d_in[6];
    const float* Wp_img    = (const float*)d_in[7];
    const float* bp_img    = (const float*)d_in[8];
    const float* Wp_radar  = (const float*)d_in[9];
    const float* bp_radar  = (const float*)d_in[10];
    float* out = (float*)d_out;

    dim3 blk(16, 16);
    dim3 gQ (NTOK / 64, CDIM / 64, BSZ);        // 36,4,4
    dim3 gKV(NTOK / 64, 2 * CDIM / 64, BSZ);    // 36,8,4

    // attn 0: q from img, kv from radar
    proj_qkv_kernel<<<gQ,  blk>>>(img,   Wq_img,    CDIM,     0, 0);
    proj_qkv_kernel<<<gKV, blk>>>(radar, Wkv_radar, 2 * CDIM, 1, 0);
    // attn 1: q from radar, kv from img
    proj_qkv_kernel<<<gQ,  blk>>>(radar, Wq_radar,  CDIM,     0, 1);
    proj_qkv_kernel<<<gKV, blk>>>(img,   Wkv_img,   2 * CDIM, 1, 1);

    dim3 gA(NTOK / 32, BSZ * NH, 2);            // 72,32,2
    attn_kernel<<<gA, 256>>>(umask);

    dim3 gO(NTOK / 64, CDIM / 64, BSZ);
    proj_out_kernel<<<gO, blk>>>(Wp_img,   bp_img,   0, out);
    proj_out_kernel<<<gO, blk>>>(Wp_radar, bp_radar, 1, out + (size_t)BSZ * CDIM * NTOK);
}

// round 2
// speedup vs baseline: 1.6175x; 1.6175x over previous
#include <cuda_runtime.h>
#include <math_constants.h>

#define NTOK 2304      // 48*48
#define CDIM 256
#define BSZ  4
#define NH   8
#define HD   32
#define SCALE 0.17677669529663687f   // 32^-0.5

typedef unsigned long long u64;
__device__ __forceinline__ u64 pk2(float lo, float hi) {
    u64 r; asm("mov.b64 %0,{%1,%2};" : "=l"(r) : "f"(lo), "f"(hi)); return r;
}
__device__ __forceinline__ void upk2(u64 v, float& lo, float& hi) {
    asm("mov.b64 {%0,%1},%2;" : "=f"(lo), "=f"(hi) : "l"(v));
}
__device__ __forceinline__ void fma2(u64& d, u64 a, u64 b) {
    asm("fma.rn.f32x2 %0,%1,%2,%0;" : "+l"(d) : "l"(a), "l"(b));
}
__device__ __forceinline__ void mul2(u64& d, u64 a) {
    asm("mul.rn.f32x2 %0,%0,%1;" : "+l"(d) : "l"(a));
}

// ---------------- scratch ----------------
__device__ float g_Q [2][BSZ*NH*NTOK*HD];   // (b,h,n,d)
__device__ float g_Kt[2][BSZ*NH*HD*NTOK];   // (b,h,d,n)
__device__ float g_V [2][BSZ*NH*NTOK*HD];   // (b,h,n,d)
__device__ float g_AttO[2][BSZ*NTOK*CDIM];  // (b,n,c)

// ---------------- QKV projection GEMM (unchanged) ----------------
__global__ void proj_qkv_kernel(const float* __restrict__ X, const float* __restrict__ W,
                                int ncol, int kind, int attn)
{
    __shared__ float As[16][64];
    __shared__ float Bs[16][64];
    const int b  = blockIdx.z;
    const int m0 = blockIdx.x * 64;
    const int n0 = blockIdx.y * 64;
    const int tx = threadIdx.x, ty = threadIdx.y;
    const int tid = ty * 16 + tx;
    const float* Xb = X + (size_t)b * CDIM * NTOK;

    float acc[4][4] = {};
    for (int k0 = 0; k0 < CDIM; k0 += 16) {
        #pragma unroll
        for (int i = tid; i < 16*64; i += 256) {
            int k = i >> 6, m = i & 63;
            As[k][m] = Xb[(size_t)(k0 + k) * NTOK + m0 + m];
        }
        #pragma unroll
        for (int i = tid; i < 16*64; i += 256) {
            int k = i >> 6, n = i & 63;
            Bs[k][n] = W[(size_t)(k0 + k) * ncol + n0 + n];
        }
        __syncthreads();
        #pragma unroll
        for (int k = 0; k < 16; k++) {
            float4 a = *(const float4*)&As[k][ty * 4];
            float4 bb = *(const float4*)&Bs[k][tx * 4];
            float av[4] = {a.x, a.y, a.z, a.w};
            float bv[4] = {bb.x, bb.y, bb.z, bb.w};
            #pragma unroll
            for (int i = 0; i < 4; i++)
                #pragma unroll
                for (int j = 0; j < 4; j++)
                    acc[i][j] += av[i] * bv[j];
        }
        __syncthreads();
    }

    float* oQ  = g_Q[attn];
    float* oKt = g_Kt[attn];
    float* oV  = g_V[attn];
    #pragma unroll
    for (int i = 0; i < 4; i++) {
        int n = m0 + ty * 4 + i;
        #pragma unroll
        for (int j = 0; j < 4; j++) {
            int cp = n0 + tx * 4 + j;
            float v = acc[i][j];
            if (kind == 0) {
                int h = cp >> 5, d = cp & 31;
                oQ[(((size_t)b * NH + h) * NTOK + n) * HD + d] = v;
            } else {
                if (cp < CDIM) {
                    int h = cp >> 5, d = cp & 31;
                    oKt[(((size_t)b * NH + h) * HD + d) * NTOK + n] = v;
                } else {
                    int c2 = cp - CDIM;
                    int h = c2 >> 5, d = c2 & 31;
                    oV[(((size_t)b * NH + h) * NTOK + n) * HD + d] = v;
                }
            }
        }
    }
}

// ---------------- attention: register-tiled flash, FFMA2 ----------------
// grid: (NTOK/64, BSZ*NH, 2). block 256 = 16x16 threads.
// Tile: 64 q-rows x 64 keys. Per thread: 4 rows (ty*4..) x 4 keys (tx*4..) for S,
// 4 rows x 2 out-dims (tx*2..) for O. Row-pair packed f32x2 accumulators.
__global__ void __launch_bounds__(256) attn_kernel(const float* __restrict__ umask)
{
    const int attn = blockIdx.z;
    const int bh   = blockIdx.y;
    const int b    = bh >> 3;
    const int h    = bh & 7;
    const int row0 = blockIdx.x * 64;

    const float* Q  = g_Q[attn];
    const float* Kt = g_Kt[attn];
    const float* V  = g_V[attn];

    __shared__ __align__(16) float Qs[HD][68];   // [d][m], pre-scaled rows
    __shared__ __align__(16) float Ks[HD][68];   // [d][j]
    __shared__ __align__(16) float Vs[64][HD];   // [j][d]
    __shared__ __align__(16) float Ps[64][68];   // [j][m]
    __shared__ float tws[64];

    const int tid = threadIdx.x;
    const int tx  = tid & 15;
    const int ty  = tid >> 4;

    if (tid < 64) {
        int n = row0 + tid;
        float f = SCALE;
        if (attn == 0) f *= 1.0f / (umask[(size_t)b * NTOK + n] + 1e-6f);
        tws[tid] = f;
    }
    __syncthreads();

    #pragma unroll
    for (int i = tid; i < 64 * HD; i += 256) {
        int m = i >> 5, d = i & 31;
        Qs[d][m] = Q[((size_t)bh * NTOK + row0 + m) * HD + d] * tws[m];
    }

    const size_t ktbase = (size_t)bh * HD * NTOK;
    const size_t vbase  = (size_t)bh * NTOK * HD;

    float runm[4], denom[4];
    #pragma unroll
    for (int i = 0; i < 4; i++) { runm[i] = -CUDART_INF_F; denom[i] = 0.f; }
    u64 oacc[2][2] = {};   // [rowpair][dcol]: {O[2p][d], O[2p+1][d]}

    for (int kb = 0; kb < NTOK; kb += 64) {
        __syncthreads();   // prior PV done with Vs/Ps
        #pragma unroll
        for (int i = tid; i < HD * 64; i += 256) {
            int d = i >> 6, j = i & 63;
            Ks[d][j] = Kt[ktbase + (size_t)d * NTOK + kb + j];
        }
        #pragma unroll
        for (int i = tid; i < 64 * HD; i += 256) {
            int j = i >> 5, d = i & 31;
            Vs[j][d] = V[vbase + (size_t)(kb + j) * HD + d];
        }
        __syncthreads();

        // ---- S = Qs^T Ks : 4x4 microtile, row-pair packed ----
        u64 sacc[2][4] = {};
        #pragma unroll
        for (int d = 0; d < HD; d++) {
            ulonglong2 av = *(const ulonglong2*)&Qs[d][ty * 4];   // rows {0,1},{2,3}
            float4 bk = *(const float4*)&Ks[d][tx * 4];
            u64 b0 = pk2(bk.x, bk.x), b1 = pk2(bk.y, bk.y);
            u64 b2 = pk2(bk.z, bk.z), b3 = pk2(bk.w, bk.w);
            fma2(sacc[0][0], av.x, b0); fma2(sacc[1][0], av.y, b0);
            fma2(sacc[0][1], av.x, b1); fma2(sacc[1][1], av.y, b1);
            fma2(sacc[0][2], av.x, b2); fma2(sacc[1][2], av.y, b2);
            fma2(sacc[0][3], av.x, b3); fma2(sacc[1][3], av.y, b3);
        }

        float s[4][4];
        #pragma unroll
        for (int p = 0; p < 2; p++)
            #pragma unroll
            for (int j = 0; j < 4; j++)
                upk2(sacc[p][j], s[2*p][j], s[2*p+1][j]);

        // ---- online softmax (row reduce over 16 tx lanes) ----
        float corrv[4];
        #pragma unroll
        for (int i = 0; i < 4; i++) {
            float mloc = fmaxf(fmaxf(s[i][0], s[i][1]), fmaxf(s[i][2], s[i][3]));
            #pragma unroll
            for (int o = 8; o > 0; o >>= 1)
                mloc = fmaxf(mloc, __shfl_xor_sync(0xffffffffu, mloc, o));
            float nm = fmaxf(runm[i], mloc);
            float corr = __expf(runm[i] - nm);
            float psum = 0.f;
            #pragma unroll
            for (int j = 0; j < 4; j++) {
                float pe = __expf(s[i][j] - nm);
                s[i][j] = pe;
                psum += pe;
            }
            #pragma unroll
            for (int o = 8; o > 0; o >>= 1)
                psum += __shfl_xor_sync(0xffffffffu, psum, o);
            denom[i] = denom[i] * corr + psum;
            runm[i] = nm;
            corrv[i] = corr;
        }
        u64 c0 = pk2(corrv[0], corrv[1]);
        u64 c1 = pk2(corrv[2], corrv[3]);
        mul2(oacc[0][0], c0); mul2(oacc[0][1], c0);
        mul2(oacc[1][0], c1); mul2(oacc[1][1], c1);

        #pragma unroll
        for (int jj = 0; jj < 4; jj++)
            *(float4*)&Ps[tx * 4 + jj][ty * 4] =
                make_float4(s[0][jj], s[1][jj], s[2][jj], s[3][jj]);
        __syncthreads();

        // ---- O += P * V : 4 rows x 2 dims, row-pair packed ----
        #pragma unroll 16
        for (int j = 0; j < 64; j++) {
            ulonglong2 pv = *(const ulonglong2*)&Ps[j][ty * 4];
            float2 vv = *(const float2*)&Vs[j][tx * 2];
            u64 vb0 = pk2(vv.x, vv.x);
            u64 vb1 = pk2(vv.y, vv.y);
            fma2(oacc[0][0], pv.x, vb0); fma2(oacc[1][0], pv.y, vb0);
            fma2(oacc[0][1], pv.x, vb1); fma2(oacc[1][1], pv.y, vb1);
        }
    }

    // ---- epilogue ----
    float o[4][2];
    #pragma unroll
    for (int p = 0; p < 2; p++)
        #pragma unroll
        for (int dd = 0; dd < 2; dd++)
            upk2(oacc[p][dd], o[2*p][dd], o[2*p+1][dd]);

    #pragma unroll
    for (int i = 0; i < 4; i++) {
        float rinv = 1.0f / denom[i];
        int n = row0 + ty * 4 + i;
        #pragma unroll
        for (int dd = 0; dd < 2; dd++)
            g_AttO[attn][((size_t)b * NTOK + n) * CDIM + h * HD + tx * 2 + dd] =
                o[i][dd] * rinv;
    }
}

// ---------------- output projection (unchanged) ----------------
__global__ void proj_out_kernel(const float* __restrict__ Wp, const float* __restrict__ bp,
                                int which, float* __restrict__ out)
{
    __shared__ float As[16][68];
    __shared__ float Bs[16][64];
    const int b  = blockIdx.z;
    const int m0 = blockIdx.x * 64;
    const int n0 = blockIdx.y * 64;
    const int tx = threadIdx.x, ty = threadIdx.y;
    const int tid = ty * 16 + tx;
    const float* A = g_AttO[which] + (size_t)b * NTOK * CDIM;

    float acc[4][4] = {};
    for (int k0 = 0; k0 < CDIM; k0 += 16) {
        #pragma unroll
        for (int i = tid; i < 16 * 64; i += 256) {
            int m = i >> 4, k = i & 15;
            As[k][m] = A[(size_t)(m0 + m) * CDIM + k0 + k];
        }
        #pragma unroll
        for (int i = tid; i < 16 * 64; i += 256) {
            int k = i >> 6, n = i & 63;
            Bs[k][n] = Wp[(size_t)(k0 + k) * CDIM + n0 + n];
        }
        __syncthreads();
        #pragma unroll
        for (int k = 0; k < 16; k++) {
            float4 a = *(const float4*)&As[k][ty * 4];
            float4 bb = *(const float4*)&Bs[k][tx * 4];
            float av[4] = {a.x, a.y, a.z, a.w};
            float bv[4] = {bb.x, bb.y, bb.z, bb.w};
            #pragma unroll
            for (int i = 0; i < 4; i++)
                #pragma unroll
                for (int j = 0; j < 4; j++)
                    acc[i][j] += av[i] * bv[j];
        }
        __syncthreads();
    }

    float* outb = out + (size_t)b * CDIM * NTOK;
    #pragma unroll
    for (int j = 0; j < 4; j++) {
        int cp = n0 + tx * 4 + j;
        float bias = bp[cp];
        #pragma unroll
        for (int i = 0; i < 4; i++) {
            int n = m0 + ty * 4 + i;
            outb[(size_t)cp * NTOK + n] = acc[i][j] + bias;
        }
    }
}

// ---------------- launch ----------------
extern "C" void kernel_launch(void* const* d_in, const int* in_sizes, int n_in,
                              void* d_out, int out_size)
{
    const float* img   = (const float*)d_in[0];
    const float* radar = (const float*)d_in[1];
    const float* umask = (const float*)d_in[2];
    const float* Wq_img    = (const float*)d_in[3];
    const float* Wkv_radar = (const float*)d_in[4];
    const float* Wq_radar  = (const float*)d_in[5];
    const float* Wkv_img   = (const float*)d_in[6];
    const float* Wp_img    = (const float*)d_in[7];
    const float* bp_img    = (const float*)d_in[8];
    const float* Wp_radar  = (const float*)d_in[9];
    const float* bp_radar  = (const float*)d_in[10];
    float* out = (float*)d_out;

    dim3 blk(16, 16);
    dim3 gQ (NTOK / 64, CDIM / 64, BSZ);
    dim3 gKV(NTOK / 64, 2 * CDIM / 64, BSZ);

    proj_qkv_kernel<<<gQ,  blk>>>(img,   Wq_img,    CDIM,     0, 0);
    proj_qkv_kernel<<<gKV, blk>>>(radar, Wkv_radar, 2 * CDIM, 1, 0);
    proj_qkv_kernel<<<gQ,  blk>>>(radar, Wq_radar,  CDIM,     0, 1);
    proj_qkv_kernel<<<gKV, blk>>>(img,   Wkv_img,   2 * CDIM, 1, 1);

    dim3 gA(NTOK / 64, BSZ * NH, 2);            // 36,32,2
    attn_kernel<<<gA, 256>>>(umask);

    dim3 gO(NTOK / 64, CDIM / 64, BSZ);
    proj_out_kernel<<<gO, blk>>>(Wp_img,   bp_img,   0, out);
    proj_out_kernel<<<gO, blk>>>(Wp_radar, bp_radar, 1, out + (size_t)BSZ * CDIM * NTOK);
}